// round 9
// baseline (speedup 1.0000x reference)
#include <cuda_runtime.h>
#include <math.h>
#include <stdint.h>

// Problem constants
#define Bb  4
#define Ss  2048
#define Dd  1024
#define Hh  16
#define HDd 64
#define Mm  (Bb*Ss)          // 8192

// Scratch (no allocation allowed -> __device__ globals)
__device__ __align__(16) float g_q[Bb*Hh*Ss*HDd];   // [B,H,S,HD] (tf32-rounded)
__device__ __align__(16) float g_k[Bb*Hh*Ss*HDd];   // (tf32-rounded)
__device__ __align__(16) float g_v[Bb*Hh*Ss*HDd];   // (tf32-rounded)
__device__ __align__(16) float g_o[Bb*Ss*Dd];       // [B,S,D] (tf32-rounded)
__device__ __align__(16) float g_xt[Mm*Dd];         // x rounded to tf32
__device__ __align__(16) float g_wt[4][Dd*Dd];      // wq,wk,wv,wo rounded

__device__ __forceinline__ uint32_t to_tf32(float f) {
    uint32_t u;
    asm("cvt.rna.tf32.f32 %0, %1;" : "=r"(u) : "f"(f));
    return u;
}

__device__ __forceinline__ void mma_tf32(float c[4],
                                         uint32_t a0, uint32_t a1, uint32_t a2, uint32_t a3,
                                         uint32_t b0, uint32_t b1) {
    asm volatile(
        "mma.sync.aligned.m16n8k8.row.col.f32.tf32.tf32.f32 "
        "{%0,%1,%2,%3}, {%4,%5,%6,%7}, {%8,%9}, {%0,%1,%2,%3};"
        : "+f"(c[0]), "+f"(c[1]), "+f"(c[2]), "+f"(c[3])
        : "r"(a0), "r"(a1), "r"(a2), "r"(a3), "r"(b0), "r"(b1));
}

__device__ __forceinline__ void cp16(void* dst_smem, const void* src) {
    uint32_t d = (uint32_t)__cvta_generic_to_shared(dst_smem);
    asm volatile("cp.async.cg.shared.global [%0], [%1], 16;\n" :: "r"(d), "l"(src));
}
#define CP_COMMIT() asm volatile("cp.async.commit_group;\n" ::: "memory")
#define CP_WAIT1()  asm volatile("cp.async.wait_group 1;\n" ::: "memory")
#define CP_WAIT0()  asm volatile("cp.async.wait_group 0;\n" ::: "memory")

// ---------------------------------------------------------------------------
// Pre-pass: round x and the 4 weight matrices to tf32 (cvt.rna), once.
// chunk = 4 floats. x: 2M chunks (blocks 0..8191); w[i]: 256K chunks each.
// ---------------------------------------------------------------------------
__global__ __launch_bounds__(256)
void round_all(const float* __restrict__ x,
               const float* __restrict__ wq, const float* __restrict__ wk,
               const float* __restrict__ wv, const float* __restrict__ wo)
{
    const int bid = blockIdx.x;
    const float* src; float* dst; size_t base;
    if (bid < 8192) { src = x; dst = g_xt; base = (size_t)bid * 1024; }
    else {
        const int w = (bid - 8192) >> 10;           // 0..3
        const int wb = (bid - 8192) & 1023;
        src = (w == 0) ? wq : (w == 1) ? wk : (w == 2) ? wv : wo;
        dst = g_wt[w]; base = (size_t)wb * 1024;
    }
    const size_t i = base + threadIdx.x * 4;
    float4 v = *(const float4*)(src + i);
    uint4 r = make_uint4(to_tf32(v.x), to_tf32(v.y), to_tf32(v.z), to_tf32(v.w));
    *(uint4*)(dst + i) = r;
}

// ---------------------------------------------------------------------------
// tf32 tensor-core GEMM, 3-stage cp.async pipeline, NO cvt in mainloop
// (inputs pre-rounded; raw bits fed to mma).
// QKV=true:  grid (24,64). blockIdx.x>>3 selects Q/K/V; A=g_xt, W=g_wt[sel],
//            out = g_q/g_k/g_v head-split [B,H,S,HD], values tf32-rounded.
// QKV=false: grid (8,64). A=g_o (pre-rounded by flash), W=g_wt[3],
//            out = d_out row-major full precision.
// ---------------------------------------------------------------------------
#define AP 20
#define BP 136
#define ASZ (128*AP)
#define BSZ (16*BP)
#define GEMM_SMEM (3*(ASZ+BSZ)*4)    // 56832 bytes

template<bool QKV>
__global__ __launch_bounds__(256, 2)
void tc_gemm(const float* __restrict__ bq, const float* __restrict__ bk,
             const float* __restrict__ bv, const float* __restrict__ bo,
             float* __restrict__ out_param)
{
    const int K = Dd, N = Dd;
    extern __shared__ float dsm[];
    float* Abuf = dsm;
    float* Bbuf = dsm + 3 * ASZ;

    int sel; const float* A; const float* W; const float* bias; float* outp;
    int bnx;
    if (QKV) {
        sel = blockIdx.x >> 3;  bnx = blockIdx.x & 7;
        A = g_xt;  W = g_wt[sel];
        bias = (sel == 0) ? bq : (sel == 1) ? bk : bv;
        outp = (sel == 0) ? g_q : (sel == 1) ? g_k : g_v;
    } else {
        sel = 3; bnx = blockIdx.x;
        A = g_o;  W = g_wt[3];  bias = bo;  outp = out_param;
    }

    const int t    = threadIdx.x;
    const int lane = t & 31;
    const int wid  = t >> 5;
    const int wm   = (wid & 3) * 32;
    const int wn   = (wid >> 2) * 64;
    const int g    = lane >> 2;
    const int tig  = lane & 3;

    const int bm = blockIdx.y * 128;
    const int bn = bnx * 128;

    const int ar = t >> 2;
    const int akc = (t & 3) * 4;
    const int brr = t >> 5;
    const int bcc = (t & 31) * 4;

    const float* Arow0 = A + (size_t)(bm + ar) * K + akc;
    const float* Arow1 = A + (size_t)(bm + ar + 64) * K + akc;
    const float* Wrow0 = W + (size_t)brr * N + bn + bcc;
    const float* Wrow1 = W + (size_t)(brr + 8) * N + bn + bcc;

    const int NT = K / 16;

    auto issue = [&](int kt, int stg) {
        if (kt < NT) {
            const int k0 = kt * 16;
            float* Asg = Abuf + stg * ASZ;
            float* Bsg = Bbuf + stg * BSZ;
            cp16(Asg + ar * AP + akc,        Arow0 + k0);
            cp16(Asg + (ar + 64) * AP + akc, Arow1 + k0);
            cp16(Bsg + brr * BP + bcc,       Wrow0 + (size_t)k0 * N);
            cp16(Bsg + (brr + 8) * BP + bcc, Wrow1 + (size_t)k0 * N);
        }
        CP_COMMIT();
    };

    float acc[2][8][4];
    #pragma unroll
    for (int ma = 0; ma < 2; ma++)
        #pragma unroll
        for (int na = 0; na < 8; na++)
            #pragma unroll
            for (int i = 0; i < 4; i++) acc[ma][na][i] = 0.f;

    issue(0, 0);
    issue(1, 1);

    for (int kt = 0; kt < NT; kt++) {
        const int cur = kt % 3;
        CP_WAIT1();
        __syncthreads();
        issue(kt + 2, (kt + 2) % 3);

        const uint32_t* Asg = (const uint32_t*)(Abuf + cur * ASZ);
        const uint32_t* Bsg = (const uint32_t*)(Bbuf + cur * BSZ);

        #pragma unroll
        for (int ks = 0; ks < 16; ks += 8) {
            uint32_t a[2][4];
            #pragma unroll
            for (int ma = 0; ma < 2; ma++) {
                const int m0 = wm + ma * 16 + g;
                a[ma][0] = Asg[(m0    ) * AP + ks + tig    ];
                a[ma][1] = Asg[(m0 + 8) * AP + ks + tig    ];
                a[ma][2] = Asg[(m0    ) * AP + ks + tig + 4];
                a[ma][3] = Asg[(m0 + 8) * AP + ks + tig + 4];
            }
            #pragma unroll
            for (int na = 0; na < 8; na++) {
                const int n0 = wn + na * 8 + g;
                uint32_t b0 = Bsg[(ks + tig    ) * BP + n0];
                uint32_t b1 = Bsg[(ks + tig + 4) * BP + n0];
                #pragma unroll
                for (int ma = 0; ma < 2; ma++)
                    mma_tf32(acc[ma][na], a[ma][0], a[ma][1], a[ma][2], a[ma][3], b0, b1);
            }
        }
    }

    // ---- epilogue: bias + store (QKV: tf32-rounded head-split) ----
    #pragma unroll
    for (int ma = 0; ma < 2; ma++) {
        #pragma unroll
        for (int na = 0; na < 8; na++) {
            const int row0 = bm + wm + ma * 16 + g;
            const int col  = bn + wn + na * 8 + tig * 2;
            const float bia0 = bias[col], bia1 = bias[col + 1];
            #pragma unroll
            for (int half = 0; half < 2; half++) {
                const int mrow = row0 + half * 8;
                const float v0 = acc[ma][na][half * 2 + 0] + bia0;
                const float v1 = acc[ma][na][half * 2 + 1] + bia1;
                if (QKV) {
                    const int b = mrow / Ss, s = mrow % Ss;
                    const int h = col / HDd, d = col % HDd;
                    uint2 r = make_uint2(to_tf32(v0), to_tf32(v1));
                    *(uint2*)&outp[(((size_t)b * Hh + h) * Ss + s) * HDd + d] = r;
                } else {
                    *(float2*)&outp[(size_t)mrow * Dd + col] = make_float2(v0, v1);
                }
            }
        }
    }
}

// ---------------------------------------------------------------------------
// Tensor-core flash attention (causal), tf32 mma, FA2-style.
// Now: K/V via cp.async (no conversion needed — inputs pre-rounded),
// double-buffered to overlap tile kt+1 load with tile kt compute.
// ---------------------------------------------------------------------------
#define KP 68
#define VP 72
#define PP 68
#define KSZ (64*KP)
#define VSZ (64*VP)
#define FA_SMEM ((2*KSZ + 2*VSZ + 4*16*PP) * 4)   // 89088 bytes

__global__ __launch_bounds__(128)
void flash_attn_tc()
{
    extern __shared__ uint32_t dsmu[];
    uint32_t* Ks = dsmu;                       // [2][64][KP]
    uint32_t* Vs = dsmu + 2 * KSZ;             // [2][64][VP]
    uint32_t* Ps = dsmu + 2 * KSZ + 2 * VSZ;   // [4][16][PP]

    const int tid  = threadIdx.x;
    const int lane = tid & 31;
    const int wid  = tid >> 5;
    const int g    = lane >> 2;
    const int tig  = lane & 3;
    const int q0   = blockIdx.x * 64;
    const int bh   = blockIdx.y;
    const int qr0  = q0 + wid * 16;

    const float* qb = g_q + (size_t)bh * Ss * HDd;
    const float* kb = g_k + (size_t)bh * Ss * HDd;
    const float* vb = g_v + (size_t)bh * Ss * HDd;

    // q pre-rounded; *0.125 is exact (power of 2) -> bits valid tf32
    uint32_t qf[8][4];
    #pragma unroll
    for (int c = 0; c < 8; c++) {
        qf[c][0] = __float_as_uint(qb[(size_t)(qr0 + g    ) * HDd + c * 8 + tig    ] * 0.125f);
        qf[c][1] = __float_as_uint(qb[(size_t)(qr0 + g + 8) * HDd + c * 8 + tig    ] * 0.125f);
        qf[c][2] = __float_as_uint(qb[(size_t)(qr0 + g    ) * HDd + c * 8 + tig + 4] * 0.125f);
        qf[c][3] = __float_as_uint(qb[(size_t)(qr0 + g + 8) * HDd + c * 8 + tig + 4] * 0.125f);
    }

    float acc[8][4];
    #pragma unroll
    for (int na = 0; na < 8; na++)
        #pragma unroll
        for (int i = 0; i < 4; i++) acc[na][i] = 0.f;

    float m_lo = -INFINITY, m_hi = -INFINITY;
    float l_lo = 0.f, l_hi = 0.f;

    uint32_t* Pw = Ps + wid * 16 * PP;
    const int nt = q0 / 64 + 1;

    auto issue_tile = [&](int kt, int buf) {
        const float* ksrc = kb + (size_t)kt * 64 * HDd;
        const float* vsrc = vb + (size_t)kt * 64 * HDd;
        uint32_t* Kd = Ks + buf * KSZ;
        uint32_t* Vd = Vs + buf * VSZ;
        #pragma unroll
        for (int i = 0; i < 8; i++) {
            const int idx = tid + i * 128;
            const int row = idx >> 4;
            const int c4  = (idx & 15) * 4;
            cp16(&Kd[row * KP + c4], ksrc + row * HDd + c4);
            cp16(&Vd[row * VP + c4], vsrc + row * HDd + c4);
        }
        CP_COMMIT();
    };

    issue_tile(0, 0);

    for (int kt = 0; kt < nt; kt++) {
        const int cur = kt & 1;
        CP_WAIT0();
        __syncthreads();
        if (kt + 1 < nt) issue_tile(kt + 1, cur ^ 1);

        const uint32_t* Kc = Ks + cur * KSZ;
        const uint32_t* Vc = Vs + cur * VSZ;

        float s[8][4];
        #pragma unroll
        for (int na = 0; na < 8; na++)
            #pragma unroll
            for (int i = 0; i < 4; i++) s[na][i] = 0.f;

        #pragma unroll
        for (int c = 0; c < 8; c++) {
            #pragma unroll
            for (int na = 0; na < 8; na++) {
                uint32_t b0 = Kc[(na * 8 + g) * KP + c * 8 + tig    ];
                uint32_t b1 = Kc[(na * 8 + g) * KP + c * 8 + tig + 4];
                mma_tf32(s[na], qf[c][0], qf[c][1], qf[c][2], qf[c][3], b0, b1);
            }
        }

        if (kt == nt - 1) {
            const int rlo = qr0 + g, rhi = qr0 + g + 8;
            #pragma unroll
            for (int na = 0; na < 8; na++) {
                const int c0 = kt * 64 + na * 8 + tig * 2;
                const int c1 = c0 + 1;
                if (c0 > rlo) s[na][0] = -INFINITY;
                if (c1 > rlo) s[na][1] = -INFINITY;
                if (c0 > rhi) s[na][2] = -INFINITY;
                if (c1 > rhi) s[na][3] = -INFINITY;
            }
        }

        float tm_lo = -INFINITY, tm_hi = -INFINITY;
        #pragma unroll
        for (int na = 0; na < 8; na++) {
            tm_lo = fmaxf(tm_lo, fmaxf(s[na][0], s[na][1]));
            tm_hi = fmaxf(tm_hi, fmaxf(s[na][2], s[na][3]));
        }
        tm_lo = fmaxf(tm_lo, __shfl_xor_sync(0xffffffffu, tm_lo, 1));
        tm_lo = fmaxf(tm_lo, __shfl_xor_sync(0xffffffffu, tm_lo, 2));
        tm_hi = fmaxf(tm_hi, __shfl_xor_sync(0xffffffffu, tm_hi, 1));
        tm_hi = fmaxf(tm_hi, __shfl_xor_sync(0xffffffffu, tm_hi, 2));

        const float mn_lo = fmaxf(m_lo, tm_lo);
        const float mn_hi = fmaxf(m_hi, tm_hi);
        const float sc_lo = __expf(m_lo - mn_lo);
        const float sc_hi = __expf(m_hi - mn_hi);

        float sum_lo = 0.f, sum_hi = 0.f;
        #pragma unroll
        for (int na = 0; na < 8; na++) {
            s[na][0] = __expf(s[na][0] - mn_lo);
            s[na][1] = __expf(s[na][1] - mn_lo);
            s[na][2] = __expf(s[na][2] - mn_hi);
            s[na][3] = __expf(s[na][3] - mn_hi);
            sum_lo += s[na][0] + s[na][1];
            sum_hi += s[na][2] + s[na][3];
        }
        sum_lo += __shfl_xor_sync(0xffffffffu, sum_lo, 1);
        sum_lo += __shfl_xor_sync(0xffffffffu, sum_lo, 2);
        sum_hi += __shfl_xor_sync(0xffffffffu, sum_hi, 1);
        sum_hi += __shfl_xor_sync(0xffffffffu, sum_hi, 2);

        l_lo = l_lo * sc_lo + sum_lo;  m_lo = mn_lo;
        l_hi = l_hi * sc_hi + sum_hi;  m_hi = mn_hi;

        #pragma unroll
        for (int na = 0; na < 8; na++) {
            acc[na][0] *= sc_lo; acc[na][1] *= sc_lo;
            acc[na][2] *= sc_hi; acc[na][3] *= sc_hi;
        }

        #pragma unroll
        for (int na = 0; na < 8; na++) {
            uint2 plo = make_uint2(to_tf32(s[na][0]), to_tf32(s[na][1]));
            uint2 phi = make_uint2(to_tf32(s[na][2]), to_tf32(s[na][3]));
            *(uint2*)&Pw[(g    ) * PP + na * 8 + tig * 2] = plo;
            *(uint2*)&Pw[(g + 8) * PP + na * 8 + tig * 2] = phi;
        }
        __syncwarp();

        #pragma unroll
        for (int c = 0; c < 8; c++) {
            uint32_t a0 = Pw[(g    ) * PP + c * 8 + tig    ];
            uint32_t a1 = Pw[(g + 8) * PP + c * 8 + tig    ];
            uint32_t a2 = Pw[(g    ) * PP + c * 8 + tig + 4];
            uint32_t a3 = Pw[(g + 8) * PP + c * 8 + tig + 4];
            #pragma unroll
            for (int na = 0; na < 8; na++) {
                uint32_t b0 = Vc[(c * 8 + tig    ) * VP + na * 8 + g];
                uint32_t b1 = Vc[(c * 8 + tig + 4) * VP + na * 8 + g];
                mma_tf32(acc[na], a0, a1, a2, a3, b0, b1);
            }
        }
    }

    // epilogue: normalize, round to tf32 (feeds O-GEMM A operand), write
    const float inv_lo = 1.f / l_lo;
    const float inv_hi = 1.f / l_hi;
    const int b = bh / Hh, h = bh % Hh;
    float* olo = g_o + ((size_t)b * Ss + (qr0 + g    )) * Dd + h * HDd;
    float* ohi = g_o + ((size_t)b * Ss + (qr0 + g + 8)) * Dd + h * HDd;
    #pragma unroll
    for (int na = 0; na < 8; na++) {
        uint2 vlo = make_uint2(to_tf32(acc[na][0] * inv_lo), to_tf32(acc[na][1] * inv_lo));
        uint2 vhi = make_uint2(to_tf32(acc[na][2] * inv_hi), to_tf32(acc[na][3] * inv_hi));
        *(uint2*)&olo[na * 8 + tig * 2] = vlo;
        *(uint2*)&ohi[na * 8 + tig * 2] = vhi;
    }
}

// ---------------------------------------------------------------------------
extern "C" void kernel_launch(void* const* d_in, const int* in_sizes, int n_in,
                              void* d_out, int out_size)
{
    const float* x  = (const float*)d_in[0];
    const float* wq = (const float*)d_in[1];
    const float* bq = (const float*)d_in[2];
    const float* wk = (const float*)d_in[3];
    const float* bk = (const float*)d_in[4];
    const float* wv = (const float*)d_in[5];
    const float* bv = (const float*)d_in[6];
    const float* wo = (const float*)d_in[7];
    const float* bo = (const float*)d_in[8];
    float* out = (float*)d_out;

    cudaFuncSetAttribute(tc_gemm<true>,  cudaFuncAttributeMaxDynamicSharedMemorySize, GEMM_SMEM);
    cudaFuncSetAttribute(tc_gemm<false>, cudaFuncAttributeMaxDynamicSharedMemorySize, GEMM_SMEM);
    cudaFuncSetAttribute(flash_attn_tc,  cudaFuncAttributeMaxDynamicSharedMemorySize, FA_SMEM);

    // pre-round x + weights to tf32
    round_all<<<8192 + 4 * 1024, 256>>>(x, wq, wk, wv, wo);

    // fused QKV projection
    dim3 qgrid(24, Mm / 128);             // (24, 64)
    tc_gemm<true><<<qgrid, 256, GEMM_SMEM>>>(bq, bk, bv, nullptr, nullptr);

    // attention
    dim3 agrid(Ss / 64, Bb * Hh);         // (32, 64)
    flash_attn_tc<<<agrid, 128, FA_SMEM>>>();

    // output projection
    dim3 ogrid(8, Mm / 128);              // (8, 64)
    tc_gemm<false><<<ogrid, 256, GEMM_SMEM>>>(nullptr, nullptr, nullptr, bo, out);
}